// round 9
// baseline (speedup 1.0000x reference)
#include <cuda_runtime.h>

// Problem constants (fixed shapes per reference)
#define NN 50000
#define DD 64
#define EE 800000
#define GG 512
#define NC 10
#define CAP 96   // padded CSR row capacity; in-degree ~ Poisson(16), P(>=96) ~ 1e-40

// ---- static device scratch (allocation-free rule: __device__ globals) ----
__device__ float g_Y [2 * NN * DD];   // per-branch GEMM output (pre-aggregation)
__device__ float g_XA[2 * NN * DD];   // per-branch features after layer 0
__device__ float g_XB[2 * NN * DD];   // per-branch features after layer 1
__device__ int   g_pad[2 * NN * CAP]; // padded CSR: src lists bucketed by dst, per edge set
__device__ int   g_cnt[2 * NN];       // in-degree per node per edge set
__device__ float g_gsum[GG * NC];
__device__ int   g_gcnt[GG];

// ---------------------------------------------------------------- init
__global__ void k_init() {
    int i = blockIdx.x * blockDim.x + threadIdx.x;
    if (i < 2 * NN) g_cnt[i] = 0;
    if (i < GG * NC) g_gsum[i] = 0.f;
    if (i < GG) g_gcnt[i] = 0;
}

// ------------------------------------------------- padded-CSR build (dst buckets)
__global__ void k_fill(const int* __restrict__ ei_sc, const int* __restrict__ ei_fc) {
    int i = blockIdx.x * blockDim.x + threadIdx.x;
    if (i >= 2 * EE) return;
    int set = (i >= EE) ? 1 : 0;
    int e = i - set * EE;
    const int* ei = set ? ei_fc : ei_sc;
    int s = __ldg(ei + e);          // edge_index[0][e] = src
    int d = __ldg(ei + EE + e);     // edge_index[1][e] = dst
    int p = atomicAdd(&g_cnt[set * NN + d], 1);
    if (p < CAP) g_pad[((size_t)set * NN + d) * CAP + p] = s;
}

// ---------------------------------------------------------------- GEMM
// Y[z] = X[z] @ W[z][layer]   (64-wide, tile 64 rows x 64 cols, 4x4 microtile)
__global__ void k_gemm(const float* __restrict__ Xext,
                       const float* __restrict__ Wz0,
                       const float* __restrict__ Wz1,
                       int layer) {
    __shared__ float Xs[64][65];     // padded stride -> conflict-free column reads
    __shared__ float Ws[64 * 64];
    int z = blockIdx.y;
    const float* X = (layer == 0) ? Xext : (g_XA + (size_t)z * NN * DD);
    const float* W = z ? Wz1 : Wz0;
    float* Yo = g_Y + (size_t)z * NN * DD;
    int row0 = blockIdx.x * 64;
    int t = threadIdx.x;

    for (int i = t; i < 1024; i += 256)
        ((float4*)Ws)[i] = ((const float4*)W)[i];
    for (int i = t; i < 1024; i += 256) {
        int r = i >> 4, c = (i & 15) * 4;
        float4 v = make_float4(0.f, 0.f, 0.f, 0.f);
        if (row0 + r < NN)
            v = *(const float4*)(X + (size_t)(row0 + r) * DD + c);
        Xs[r][c]     = v.x; Xs[r][c + 1] = v.y;
        Xs[r][c + 2] = v.z; Xs[r][c + 3] = v.w;
    }
    __syncthreads();

    int tx = t & 15, ty = t >> 4;
    int c0 = tx * 4, r0 = ty * 4;
    float acc[4][4];
#pragma unroll
    for (int i = 0; i < 4; i++)
#pragma unroll
        for (int j = 0; j < 4; j++) acc[i][j] = 0.f;

#pragma unroll 16
    for (int k = 0; k < 64; k++) {
        float4 w = *(const float4*)&Ws[k * 64 + c0];
        float a0 = Xs[r0 + 0][k];
        float a1 = Xs[r0 + 1][k];
        float a2 = Xs[r0 + 2][k];
        float a3 = Xs[r0 + 3][k];
        acc[0][0] += a0 * w.x; acc[0][1] += a0 * w.y; acc[0][2] += a0 * w.z; acc[0][3] += a0 * w.w;
        acc[1][0] += a1 * w.x; acc[1][1] += a1 * w.y; acc[1][2] += a1 * w.z; acc[1][3] += a1 * w.w;
        acc[2][0] += a2 * w.x; acc[2][1] += a2 * w.y; acc[2][2] += a2 * w.z; acc[2][3] += a2 * w.w;
        acc[3][0] += a3 * w.x; acc[3][1] += a3 * w.y; acc[3][2] += a3 * w.z; acc[3][3] += a3 * w.w;
    }
#pragma unroll
    for (int i = 0; i < 4; i++) {
        int r = row0 + r0 + i;
        if (r < NN)
            *(float4*)(Yo + (size_t)r * DD + c0) =
                make_float4(acc[i][0], acc[i][1], acc[i][2], acc[i][3]);
    }
}

// ----------------------------------------------- aggregation + scale + bias + relu
// Xout[z][d] = relu( (1/max(deg,1)) * sum_{s in row(d)} Y[z][s] + bias_z )
// warp per (branch, dst-node); lane covers 2 features via float2 (coalesced 256B rows)
// 8 edges in flight per iteration -> MLP_eff ~8 to hide L2 latency (234-262 cyc)
__global__ void k_agg(const float* __restrict__ bias0,
                      const float* __restrict__ bias1,
                      int layer) {
    int gw = (blockIdx.x * blockDim.x + threadIdx.x) >> 5;
    int lane = threadIdx.x & 31;
    if (gw >= 2 * NN) return;
    int z = (gw >= NN) ? 1 : 0;
    int node = gw - z * NN;

    const float* y = g_Y + (size_t)z * NN * DD;
    const int* rowp = g_pad + ((size_t)z * NN + node) * CAP;
    int cnt = g_cnt[z * NN + node];
    int m = min(cnt, CAP);

    float a0 = 0.f, a1 = 0.f;
    float b0a = 0.f, b1a = 0.f;
    int f = lane * 2;
    int e = 0;
    for (; e + 8 <= m; e += 8) {
        int4 sa = *(const int4*)(rowp + e);       // uniform across warp -> broadcast
        int4 sb = *(const int4*)(rowp + e + 4);
        float2 v0 = __ldg((const float2*)(y + (size_t)sa.x * DD + f));
        float2 v1 = __ldg((const float2*)(y + (size_t)sa.y * DD + f));
        float2 v2 = __ldg((const float2*)(y + (size_t)sa.z * DD + f));
        float2 v3 = __ldg((const float2*)(y + (size_t)sa.w * DD + f));
        float2 v4 = __ldg((const float2*)(y + (size_t)sb.x * DD + f));
        float2 v5 = __ldg((const float2*)(y + (size_t)sb.y * DD + f));
        float2 v6 = __ldg((const float2*)(y + (size_t)sb.z * DD + f));
        float2 v7 = __ldg((const float2*)(y + (size_t)sb.w * DD + f));
        a0  += (v0.x + v1.x) + (v2.x + v3.x);
        a1  += (v0.y + v1.y) + (v2.y + v3.y);
        b0a += (v4.x + v5.x) + (v6.x + v7.x);
        b1a += (v4.y + v5.y) + (v6.y + v7.y);
    }
    for (; e + 4 <= m; e += 4) {
        int4 s4 = *(const int4*)(rowp + e);
        float2 v0 = __ldg((const float2*)(y + (size_t)s4.x * DD + f));
        float2 v1 = __ldg((const float2*)(y + (size_t)s4.y * DD + f));
        float2 v2 = __ldg((const float2*)(y + (size_t)s4.z * DD + f));
        float2 v3 = __ldg((const float2*)(y + (size_t)s4.w * DD + f));
        a0 += (v0.x + v1.x) + (v2.x + v3.x);
        a1 += (v0.y + v1.y) + (v2.y + v3.y);
    }
    for (; e < m; e++) {
        float2 v = __ldg((const float2*)(y + (size_t)rowp[e] * DD + f));
        a0 += v.x; a1 += v.y;
    }
    a0 += b0a; a1 += b1a;

    float inv = 1.f / (float)max(cnt, 1);
    const float* bias = z ? bias1 : bias0;
    float r0 = fmaxf(fmaf(a0, inv, bias[f]),     0.f);
    float r1 = fmaxf(fmaf(a1, inv, bias[f + 1]), 0.f);
    float* Xout = (layer == 0) ? g_XA : g_XB;
    *(float2*)(Xout + ((size_t)z * NN + node) * DD + f) = make_float2(r0, r1);
}

// ------------------------------------- fuse branches + output proj + graph pooling
__global__ void k_out(const float* __restrict__ Wout, const int* __restrict__ batch) {
    __shared__ float Ws[DD * NC];
    for (int i = threadIdx.x; i < DD * NC; i += blockDim.x) Ws[i] = Wout[i];
    __syncthreads();

    int gw = (blockIdx.x * blockDim.x + threadIdx.x) >> 5;
    int lane = threadIdx.x & 31;
    if (gw >= NN) return;

    const float* p0 = g_XB + (size_t)gw * DD;
    const float* p1 = g_XB + ((size_t)NN + gw) * DD;
    int f = lane * 2;
    float2 u0 = *(const float2*)(p0 + f);
    float2 u1 = *(const float2*)(p1 + f);
    float ha = 0.5f * (u0.x + u1.x);   // feature f
    float hb = 0.5f * (u0.y + u1.y);   // feature f+1
    int g = batch[gw];

#pragma unroll
    for (int j = 0; j < NC; j++) {
        float p = ha * Ws[f * NC + j] + hb * Ws[(f + 1) * NC + j];
        p += __shfl_down_sync(0xffffffff, p, 16);
        p += __shfl_down_sync(0xffffffff, p, 8);
        p += __shfl_down_sync(0xffffffff, p, 4);
        p += __shfl_down_sync(0xffffffff, p, 2);
        p += __shfl_down_sync(0xffffffff, p, 1);
        if (lane == 0) atomicAdd(&g_gsum[g * NC + j], p);
    }
    if (lane == 0) atomicAdd(&g_gcnt[g], 1);
}

__global__ void k_div(const float* __restrict__ bout, float* __restrict__ out) {
    int i = blockIdx.x * blockDim.x + threadIdx.x;
    if (i < GG * NC) {
        int g = i / NC, j = i - g * NC;
        out[i] = g_gsum[i] / (float)max(g_gcnt[g], 1) + bout[j];
    }
}

// ---------------------------------------------------------------- launch
extern "C" void kernel_launch(void* const* d_in, const int* in_sizes, int n_in,
                              void* d_out, int out_size) {
    const float* x    = (const float*)d_in[0];
    const float* W0   = (const float*)d_in[1];   // [2,64,64]
    const float* b0   = (const float*)d_in[2];   // [2,64]
    const float* W1   = (const float*)d_in[3];
    const float* b1   = (const float*)d_in[4];
    const float* Wout = (const float*)d_in[5];   // [64,10]
    const float* bout = (const float*)d_in[6];   // [10]
    const int*  ei_sc = (const int*)d_in[7];     // [2,E]
    const int*  ei_fc = (const int*)d_in[8];     // [2,E]
    const int*  batch = (const int*)d_in[9];     // [N]
    float* out = (float*)d_out;
    (void)in_sizes; (void)n_in; (void)out_size;

    k_init<<<(2 * NN + 255) / 256, 256>>>();
    k_fill<<<(2 * EE + 255) / 256, 256>>>(ei_sc, ei_fc);

    dim3 gg((NN + 63) / 64, 2);
    int agg_blocks = (2 * NN * 32 + 255) / 256;

    // layer 0: y = x @ W[0]  (same input x for both branches), then agg -> XA
    k_gemm<<<gg, 256>>>(x, W0, W1, 0);
    k_agg<<<agg_blocks, 256>>>(b0, b1, 0);

    // layer 1: y = XA @ W[1], then agg -> XB
    k_gemm<<<gg, 256>>>(x /*unused*/, W0 + DD * DD, W1 + DD * DD, 1);
    k_agg<<<agg_blocks, 256>>>(b0 + DD, b1 + DD, 1);

    // fuse + project + pool
    k_out<<<(NN * 32 + 255) / 256, 256>>>(Wout, batch);
    k_div<<<(GG * NC + 255) / 256, 256>>>(bout, out);
}

// round 13
// speedup vs baseline: 1.0447x; 1.0447x over previous
#include <cuda_runtime.h>
#include <cuda_fp16.h>

// Problem constants (fixed shapes per reference)
#define NN 50000
#define DD 64
#define EE 800000
#define GG 512
#define NC 10
#define CAP 96   // padded CSR row capacity; in-degree ~ Poisson(16), P(>=96) ~ 1e-40

// ---- static device scratch (allocation-free rule: __device__ globals) ----
__device__ __half2 g_Y[2 * NN * 32]; // per-branch GEMM output, fp16x2 (32 half2 per row)
__device__ float g_XA[2 * NN * DD];  // per-branch features after layer 0 (fp32)
__device__ float g_XB[2 * NN * DD];  // per-branch features after layer 1 (fp32)
__device__ int   g_pad[2 * NN * CAP]; // padded CSR: src*32 (premultiplied half2 offset)
__device__ int   g_cnt[2 * NN];       // in-degree per node per edge set
__device__ float g_gsum[GG * NC];
__device__ int   g_gcnt[GG];

// ---------------------------------------------------------------- init
__global__ void k_init() {
    int i = blockIdx.x * blockDim.x + threadIdx.x;
    if (i < 2 * NN) g_cnt[i] = 0;
    if (i < GG * NC) g_gsum[i] = 0.f;
    if (i < GG) g_gcnt[i] = 0;
}

// ------------------------------------------------- padded-CSR build (dst buckets)
// stores src*32 so the gather loop needs zero per-edge multiplies
__global__ void k_fill(const int* __restrict__ ei_sc, const int* __restrict__ ei_fc) {
    int i = blockIdx.x * blockDim.x + threadIdx.x;
    if (i >= 2 * EE) return;
    int set = (i >= EE) ? 1 : 0;
    int e = i - set * EE;
    const int* ei = set ? ei_fc : ei_sc;
    int s = __ldg(ei + e);          // edge_index[0][e] = src
    int d = __ldg(ei + EE + e);     // edge_index[1][e] = dst
    int p = atomicAdd(&g_cnt[set * NN + d], 1);
    if (p < CAP) g_pad[((size_t)set * NN + d) * CAP + p] = s * 32;
}

// ---------------------------------------------------------------- GEMM
// Y[z] = X[z] @ W[z][layer]  (fp32 compute, fp16 output for cheap gathers)
__global__ void k_gemm(const float* __restrict__ Xext,
                       const float* __restrict__ Wz0,
                       const float* __restrict__ Wz1,
                       int layer) {
    __shared__ float Xs[64][65];     // padded stride -> conflict-free column reads
    __shared__ float Ws[64 * 64];
    int z = blockIdx.y;
    const float* X = (layer == 0) ? Xext : (g_XA + (size_t)z * NN * DD);
    const float* W = z ? Wz1 : Wz0;
    __half2* Yo = g_Y + (size_t)z * NN * 32;
    int row0 = blockIdx.x * 64;
    int t = threadIdx.x;

    for (int i = t; i < 1024; i += 256)
        ((float4*)Ws)[i] = ((const float4*)W)[i];
    for (int i = t; i < 1024; i += 256) {
        int r = i >> 4, c = (i & 15) * 4;
        float4 v = make_float4(0.f, 0.f, 0.f, 0.f);
        if (row0 + r < NN)
            v = *(const float4*)(X + (size_t)(row0 + r) * DD + c);
        Xs[r][c]     = v.x; Xs[r][c + 1] = v.y;
        Xs[r][c + 2] = v.z; Xs[r][c + 3] = v.w;
    }
    __syncthreads();

    int tx = t & 15, ty = t >> 4;
    int c0 = tx * 4, r0 = ty * 4;
    float acc[4][4];
#pragma unroll
    for (int i = 0; i < 4; i++)
#pragma unroll
        for (int j = 0; j < 4; j++) acc[i][j] = 0.f;

#pragma unroll 16
    for (int k = 0; k < 64; k++) {
        float4 w = *(const float4*)&Ws[k * 64 + c0];
        float a0 = Xs[r0 + 0][k];
        float a1 = Xs[r0 + 1][k];
        float a2 = Xs[r0 + 2][k];
        float a3 = Xs[r0 + 3][k];
        acc[0][0] += a0 * w.x; acc[0][1] += a0 * w.y; acc[0][2] += a0 * w.z; acc[0][3] += a0 * w.w;
        acc[1][0] += a1 * w.x; acc[1][1] += a1 * w.y; acc[1][2] += a1 * w.z; acc[1][3] += a1 * w.w;
        acc[2][0] += a2 * w.x; acc[2][1] += a2 * w.y; acc[2][2] += a2 * w.z; acc[2][3] += a2 * w.w;
        acc[3][0] += a3 * w.x; acc[3][1] += a3 * w.y; acc[3][2] += a3 * w.z; acc[3][3] += a3 * w.w;
    }
#pragma unroll
    for (int i = 0; i < 4; i++) {
        int r = row0 + r0 + i;
        if (r < NN) {
            __half2 h0 = __floats2half2_rn(acc[i][0], acc[i][1]);
            __half2 h1 = __floats2half2_rn(acc[i][2], acc[i][3]);
            __half2* dst = Yo + (size_t)r * 32 + tx * 2;  // 8B-aligned pair
            dst[0] = h0;
            dst[1] = h1;
        }
    }
}

// ----------------------------------------------- aggregation + scale + bias + relu
// Xout[z][d] = relu( (1/max(deg,1)) * sum_{s in row(d)} Y[z][s] + bias_z )
// warp per (branch, dst-node); lane reads ONE half2 (features 2l,2l+1)
// -> 128B/warp/edge = 1 L1 wavefront; 8 edges in flight; fp32 accumulation
__global__ void k_agg(const float* __restrict__ bias0,
                      const float* __restrict__ bias1,
                      int layer) {
    int gw = (blockIdx.x * blockDim.x + threadIdx.x) >> 5;
    int lane = threadIdx.x & 31;
    if (gw >= 2 * NN) return;
    int z = (gw >= NN) ? 1 : 0;
    int node = gw - z * NN;

    const __half2* y = g_Y + (size_t)z * NN * 32 + lane;  // lane folded into base
    const int* rowp = g_pad + ((size_t)z * NN + node) * CAP;
    int cnt = g_cnt[z * NN + node];
    int m = min(cnt, CAP);

    float a0 = 0.f, a1 = 0.f;
    float b0a = 0.f, b1a = 0.f;
    int e = 0;
    for (; e + 8 <= m; e += 8) {
        int4 sa = *(const int4*)(rowp + e);       // premultiplied offsets, warp-uniform
        int4 sb = *(const int4*)(rowp + e + 4);
        __half2 h0 = __ldg(y + sa.x);
        __half2 h1 = __ldg(y + sa.y);
        __half2 h2 = __ldg(y + sa.z);
        __half2 h3 = __ldg(y + sa.w);
        __half2 h4 = __ldg(y + sb.x);
        __half2 h5 = __ldg(y + sb.y);
        __half2 h6 = __ldg(y + sb.z);
        __half2 h7 = __ldg(y + sb.w);
        float2 v0 = __half22float2(h0);
        float2 v1 = __half22float2(h1);
        float2 v2 = __half22float2(h2);
        float2 v3 = __half22float2(h3);
        float2 v4 = __half22float2(h4);
        float2 v5 = __half22float2(h5);
        float2 v6 = __half22float2(h6);
        float2 v7 = __half22float2(h7);
        a0  += (v0.x + v1.x) + (v2.x + v3.x);
        a1  += (v0.y + v1.y) + (v2.y + v3.y);
        b0a += (v4.x + v5.x) + (v6.x + v7.x);
        b1a += (v4.y + v5.y) + (v6.y + v7.y);
    }
    for (; e + 4 <= m; e += 4) {
        int4 s4 = *(const int4*)(rowp + e);
        float2 v0 = __half22float2(__ldg(y + s4.x));
        float2 v1 = __half22float2(__ldg(y + s4.y));
        float2 v2 = __half22float2(__ldg(y + s4.z));
        float2 v3 = __half22float2(__ldg(y + s4.w));
        a0 += (v0.x + v1.x) + (v2.x + v3.x);
        a1 += (v0.y + v1.y) + (v2.y + v3.y);
    }
    for (; e < m; e++) {
        float2 v = __half22float2(__ldg(y + rowp[e]));
        a0 += v.x; a1 += v.y;
    }
    a0 += b0a; a1 += b1a;

    int f = lane * 2;
    float inv = 1.f / (float)max(cnt, 1);
    const float* bias = z ? bias1 : bias0;
    float r0 = fmaxf(fmaf(a0, inv, bias[f]),     0.f);
    float r1 = fmaxf(fmaf(a1, inv, bias[f + 1]), 0.f);
    float* Xout = (layer == 0) ? g_XA : g_XB;
    *(float2*)(Xout + ((size_t)z * NN + node) * DD + f) = make_float2(r0, r1);
}

// ------------------------------------- fuse branches + output proj + graph pooling
__global__ void k_out(const float* __restrict__ Wout, const int* __restrict__ batch) {
    __shared__ float Ws[DD * NC];
    for (int i = threadIdx.x; i < DD * NC; i += blockDim.x) Ws[i] = Wout[i];
    __syncthreads();

    int gw = (blockIdx.x * blockDim.x + threadIdx.x) >> 5;
    int lane = threadIdx.x & 31;
    if (gw >= NN) return;

    const float* p0 = g_XB + (size_t)gw * DD;
    const float* p1 = g_XB + ((size_t)NN + gw) * DD;
    int f = lane * 2;
    float2 u0 = *(const float2*)(p0 + f);
    float2 u1 = *(const float2*)(p1 + f);
    float ha = 0.5f * (u0.x + u1.x);   // feature f
    float hb = 0.5f * (u0.y + u1.y);   // feature f+1
    int g = batch[gw];

#pragma unroll
    for (int j = 0; j < NC; j++) {
        float p = ha * Ws[f * NC + j] + hb * Ws[(f + 1) * NC + j];
        p += __shfl_down_sync(0xffffffff, p, 16);
        p += __shfl_down_sync(0xffffffff, p, 8);
        p += __shfl_down_sync(0xffffffff, p, 4);
        p += __shfl_down_sync(0xffffffff, p, 2);
        p += __shfl_down_sync(0xffffffff, p, 1);
        if (lane == 0) atomicAdd(&g_gsum[g * NC + j], p);
    }
    if (lane == 0) atomicAdd(&g_gcnt[g], 1);
}

__global__ void k_div(const float* __restrict__ bout, float* __restrict__ out) {
    int i = blockIdx.x * blockDim.x + threadIdx.x;
    if (i < GG * NC) {
        int g = i / NC, j = i - g * NC;
        out[i] = g_gsum[i] / (float)max(g_gcnt[g], 1) + bout[j];
    }
}

// ---------------------------------------------------------------- launch
extern "C" void kernel_launch(void* const* d_in, const int* in_sizes, int n_in,
                              void* d_out, int out_size) {
    const float* x    = (const float*)d_in[0];
    const float* W0   = (const float*)d_in[1];   // [2,64,64]
    const float* b0   = (const float*)d_in[2];   // [2,64]
    const float* W1   = (const float*)d_in[3];
    const float* b1   = (const float*)d_in[4];
    const float* Wout = (const float*)d_in[5];   // [64,10]
    const float* bout = (const float*)d_in[6];   // [10]
    const int*  ei_sc = (const int*)d_in[7];     // [2,E]
    const int*  ei_fc = (const int*)d_in[8];     // [2,E]
    const int*  batch = (const int*)d_in[9];     // [N]
    float* out = (float*)d_out;
    (void)in_sizes; (void)n_in; (void)out_size;

    k_init<<<(2 * NN + 255) / 256, 256>>>();
    k_fill<<<(2 * EE + 255) / 256, 256>>>(ei_sc, ei_fc);

    dim3 gg((NN + 63) / 64, 2);
    int agg_blocks = (2 * NN * 32 + 255) / 256;

    // layer 0: y = x @ W[0]  (same input x for both branches), then agg -> XA
    k_gemm<<<gg, 256>>>(x, W0, W1, 0);
    k_agg<<<agg_blocks, 256>>>(b0, b1, 0);

    // layer 1: y = XA @ W[1], then agg -> XB
    k_gemm<<<gg, 256>>>(x /*unused*/, W0 + DD * DD, W1 + DD * DD, 1);
    k_agg<<<agg_blocks, 256>>>(b0 + DD, b1 + DD, 1);

    // fuse + project + pool
    k_out<<<(NN * 32 + 255) / 256, 256>>>(Wout, batch);
    k_div<<<(GG * NC + 255) / 256, 256>>>(bout, out);
}